// round 5
// baseline (speedup 1.0000x reference)
#include <cuda_runtime.h>
#include <cuda_bf16.h>
#include <cstdint>

// Problem constants
#define CC   32
#define HH   80
#define WW   80
#define KK   4
#define HP   77            // HH-KK+1
#define NP   (HP*HP)       // 5929 patches
#define DD   (CC*KK*KK)    // 512
#define MW   81            // mask width (H+1)
#define EPSF 1e-6f
#define HW   (HH*WW)

// ---------------- device scratch (allocation-free rule) ----------------------
// 3-way bf16 limb matrices, patch-major [idx][512]
__device__ __align__(16) __nv_bfloat16 g_Ah[NP * DD];  // queries (high) limbs
__device__ __align__(16) __nv_bfloat16 g_Am[NP * DD];
__device__ __align__(16) __nv_bfloat16 g_Al[NP * DD];
__device__ __align__(16) __nv_bfloat16 g_Bh[NP * DD];  // candidates (low) limbs
__device__ __align__(16) __nv_bfloat16 g_Bm[NP * DD];
__device__ __align__(16) __nv_bfloat16 g_Bl[NP * DD];
__device__ float              g_s1[HW];
__device__ float              g_invnorm[NP];
__device__ unsigned char      g_valid[NP];
__device__ unsigned long long g_keys[NP];
__device__ int                g_qlist[NP];
__device__ int                g_clist[NP];
__device__ int                g_qcount;
__device__ int                g_ccount;

// ---------------- helpers -----------------------------------------------------
__device__ __forceinline__ unsigned mono(float f) {
    unsigned b = __float_as_uint(f);
    return (b & 0x80000000u) ? ~b : (b | 0x80000000u);
}
__device__ __forceinline__ uint32_t smem_u32(const void* p) {
    uint32_t a;
    asm("{ .reg .u64 t; cvta.to.shared.u64 t, %1; cvt.u32.u64 %0, t; }"
        : "=r"(a) : "l"(p));
    return a;
}
__device__ __forceinline__ void mma16816(float* c, const uint32_t* a, const uint32_t* b) {
    asm volatile(
        "mma.sync.aligned.m16n8k16.row.col.f32.bf16.bf16.f32 "
        "{%0,%1,%2,%3}, {%4,%5,%6,%7}, {%8,%9}, {%0,%1,%2,%3};"
        : "+f"(c[0]), "+f"(c[1]), "+f"(c[2]), "+f"(c[3])
        : "r"(a[0]), "r"(a[1]), "r"(a[2]), "r"(a[3]), "r"(b[0]), "r"(b[1]));
}

// smem layout for the GEMM kernel (dynamic)
#define SM_CINV   0
#define SM_CORIG  256
#define SM_QS     512
#define SM_BUFA   1024
#define BUFA_SZ   49152     // 3 limbs x 128 rows x 128B
#define SM_BUFB   (SM_BUFA + BUFA_SZ)
#define BUFB_SZ   24576     // 3 limbs x 64 rows x 128B
#define SMEM_TOTAL (SM_BUFB + BUFB_SZ)

// ---------------- K1: per-pixel channel sum of squares (+ counter reset) -----
__global__ void sumsq_kernel(const float* __restrict__ low) {
    int pix = blockIdx.x * blockDim.x + threadIdx.x;
    if (pix == 0) { g_qcount = 0; g_ccount = 0; }
    if (pix >= HW) return;
    float s = 0.f;
    #pragma unroll
    for (int c = 0; c < CC; c++) { float v = low[c * HW + pix]; s += v * v; }
    g_s1[pix] = s;
}

// ---------------- K2: per-patch stats (norm, valid, compaction lists) --------
__global__ void stats_kernel(const int* __restrict__ mask) {
    int p = blockIdx.x * blockDim.x + threadIdx.x;
    if (p >= NP) return;
    int pi = p / HP, pj = p % HP;
    float ns = 0.f;
    #pragma unroll
    for (int di = 0; di < KK; di++)
        #pragma unroll
        for (int dj = 0; dj < KK; dj++)
            ns += g_s1[(pi + di) * WW + (pj + dj)];
    g_invnorm[p] = 1.0f / (sqrtf(ns) + EPSF);
    g_keys[p] = ((unsigned long long)mono(-1e9f) << 32) | 0xFFFFFFFFull; // cand=0 fallback
    int m00 = mask[pi * MW + pj];
    if (m00 != 1) {                       // candidate: not excluded
        int slot = atomicAdd(&g_ccount, 1);
        g_clist[slot] = p;
    }
    int v = (m00 != 0) && (mask[pi * MW + pj + KK] != 0) &&
            (mask[(pi + KK) * MW + pj] != 0) && (mask[(pi + KK) * MW + pj + KK] != 0);
    g_valid[p] = (unsigned char)v;
    if (v) {
        int slot = atomicAdd(&g_qcount, 1);
        g_qlist[slot] = p;
    }
}

// ---------------- K3: gather + 3-way bf16 split, block = 2 patches -----------
__global__ void gather_split_kernel(const float* __restrict__ low,
                                    const float* __restrict__ high) {
    int fam  = blockIdx.y;                          // 0 = candidates, 1 = queries
    int n    = fam ? g_qcount : g_ccount;
    int pidx = blockIdx.x * 2 + (threadIdx.x >> 7);
    if (pidx >= n) return;
    const int*   list = fam ? g_qlist : g_clist;
    const float* src  = fam ? high : low;
    __nv_bfloat16* dh = fam ? g_Ah : g_Bh;
    __nv_bfloat16* dm = fam ? g_Am : g_Bm;
    __nv_bfloat16* dl = fam ? g_Al : g_Bl;

    int p  = list[pidx];
    int pi = p / HP, pj = p % HP;
    int t  = threadIdx.x & 127;
    int d  = t * 4;                       // 4 consecutive elems: same c, di; dj=0..3
    int c  = d >> 4, di = (d >> 2) & 3;
    const float* rp = src + c * HW + (pi + di) * WW + pj;

    unsigned short hb[4], mb[4], lb[4];
    #pragma unroll
    for (int e = 0; e < 4; e++) {
        float x = rp[e];
        __nv_bfloat16 h = __float2bfloat16_rn(x);
        float r1 = x - __bfloat162float(h);
        __nv_bfloat16 m = __float2bfloat16_rn(r1);
        float r2 = r1 - __bfloat162float(m);
        __nv_bfloat16 l = __float2bfloat16_rn(r2);
        hb[e] = *(unsigned short*)&h;
        mb[e] = *(unsigned short*)&m;
        lb[e] = *(unsigned short*)&l;
    }
    size_t off = (size_t)pidx * DD + d;
    *(ushort4*)(dh + off) = make_ushort4(hb[0], hb[1], hb[2], hb[3]);
    *(ushort4*)(dm + off) = make_ushort4(mb[0], mb[1], mb[2], mb[3]);
    *(ushort4*)(dl + off) = make_ushort4(lb[0], lb[1], lb[2], lb[3]);
}

// ---------------- K4: mma.sync GEMM (6-pass 3-limb bf16) + fused argmax ------
// 256 threads (8 warps); tile = 128 queries x 64 candidates; K chunked by 64.
__global__ void __launch_bounds__(256, 1) gemm_mma_kernel() {
    extern __shared__ __align__(1024) char smem[];
    float* cinv  = (float*)(smem + SM_CINV);
    int*   corig = (int*)(smem + SM_CORIG);
    int*   qs    = (int*)(smem + SM_QS);
    char*  bufA  = smem + SM_BUFA;
    char*  bufB  = smem + SM_BUFB;
    const uint32_t sA = smem_u32(bufA);
    const uint32_t sB = smem_u32(bufB);

    const int tid = threadIdx.x;
    const int w   = tid >> 5;
    const int l   = tid & 31;

    const int nq = g_qcount, nc = g_ccount;
    const int qt = (nq + 127) >> 7, ct = (nc + 63) >> 6;
    const int ntiles = (nq > 0 && nc > 0) ? qt * ct : 0;

    const __nv_bfloat16* Asrc[3] = {g_Ah, g_Am, g_Al};
    const __nv_bfloat16* Bsrc[3] = {g_Bh, g_Bm, g_Bl};

    // copy-role indices
    const int ar = tid >> 1, ah = tid & 1;        // A: 2 threads per row, 64B each
    const int br = tid >> 2, bq = tid & 3;        // B: 4 threads per row, 32B each

    // ldmatrix addresses (fixed per thread, chunk-dependent part added in loop)
    const int arow = w * 16 + (l & 15);
    const int brow_lo = l & 7;
    const int bsel_hi = (l >> 3) & 1;

    for (int t = blockIdx.x; t < ntiles; t += gridDim.x) {
        const int qb = t / ct, cb = t - qb * ct;
        __syncthreads();                 // protect prev tile's smem reads
        if (tid < 64) {
            int ci = cb * 64 + tid;
            int co = (ci < nc) ? g_clist[ci] : 0;
            corig[tid] = co;
            cinv[tid]  = (ci < nc) ? g_invnorm[co] : 0.f;
        }
        if (tid < 128) {
            int qi2 = qb * 128 + tid;
            qs[tid] = (qi2 < nq) ? g_qlist[qi2] : -1;
        }

        float acc[8][4];
        #pragma unroll
        for (int nb = 0; nb < 8; nb++)
            #pragma unroll
            for (int e = 0; e < 4; e++) acc[nb][e] = 0.f;

        for (int s = 0; s < 8; s++) {
            __syncthreads();
            // A chunk: [3][128 rows][64 bf16], swizzled 16B chunks
            #pragma unroll
            for (int ss = 0; ss < 3; ss++) {
                const uint4* src = (const uint4*)((const char*)Asrc[ss] +
                    (size_t)(qb * 128 + ar) * (DD * 2) + s * 128 + ah * 64);
                char* dst = bufA + ss * 16384 + ar * 128;
                #pragma unroll
                for (int i = 0; i < 4; i++) {
                    int c = ah * 4 + i;
                    *(uint4*)(dst + ((c ^ (ar & 7)) * 16)) = src[i];
                }
            }
            // B chunk: [3][64 rows][64 bf16]
            #pragma unroll
            for (int ss = 0; ss < 3; ss++) {
                const uint4* src = (const uint4*)((const char*)Bsrc[ss] +
                    (size_t)(cb * 64 + br) * (DD * 2) + s * 128 + bq * 32);
                char* dst = bufB + ss * 8192 + br * 128;
                #pragma unroll
                for (int i = 0; i < 2; i++) {
                    int c = bq * 2 + i;
                    *(uint4*)(dst + ((c ^ (br & 7)) * 16)) = src[i];
                }
            }
            __syncthreads();
            // compute 4 k16-steps
            #pragma unroll
            for (int kk = 0; kk < 4; kk++) {
                uint32_t af[3][4];
                int achunk = 2 * kk + (l >> 4);
                uint32_t aaddr = sA + arow * 128 + ((achunk ^ (arow & 7)) * 16);
                #pragma unroll
                for (int ss = 0; ss < 3; ss++)
                    asm volatile("ldmatrix.sync.aligned.m8n8.x4.shared.b16 "
                                 "{%0,%1,%2,%3}, [%4];"
                                 : "=r"(af[ss][0]), "=r"(af[ss][1]),
                                   "=r"(af[ss][2]), "=r"(af[ss][3])
                                 : "r"(aaddr + ss * 16384));
                #pragma unroll
                for (int nb = 0; nb < 8; nb++) {
                    uint32_t bf[3][2];
                    int brow = nb * 8 + brow_lo;
                    int bchunk = 2 * kk + bsel_hi;
                    uint32_t baddr = sB + brow * 128 + ((bchunk ^ (brow & 7)) * 16);
                    #pragma unroll
                    for (int ss = 0; ss < 3; ss++)
                        asm volatile("ldmatrix.sync.aligned.m8n8.x2.shared.b16 "
                                     "{%0,%1}, [%2];"
                                     : "=r"(bf[ss][0]), "=r"(bf[ss][1])
                                     : "r"(baddr + ss * 8192));
                    mma16816(acc[nb], af[0], bf[0]);   // h*h
                    mma16816(acc[nb], af[0], bf[1]);   // h*m
                    mma16816(acc[nb], af[1], bf[0]);   // m*h
                    mma16816(acc[nb], af[1], bf[1]);   // m*m
                    mma16816(acc[nb], af[0], bf[2]);   // h*l
                    mma16816(acc[nb], af[2], bf[0]);   // l*h
                }
            }
        }

        // epilogue: fragment rows -> argmax keys
        int jmax = nc - cb * 64; if (jmax > 64) jmax = 64;
        #pragma unroll
        for (int h2 = 0; h2 < 2; h2++) {
            int rowm = w * 16 + (l >> 2) + h2 * 8;
            unsigned long long best = 0ull;
            #pragma unroll
            for (int nb = 0; nb < 8; nb++) {
                #pragma unroll
                for (int e = 0; e < 2; e++) {
                    int nloc = nb * 8 + (l & 3) * 2 + e;
                    if (nloc < jmax) {
                        float sc = acc[nb][h2 * 2 + e] * cinv[nloc];
                        unsigned long long key =
                            ((unsigned long long)mono(sc) << 32) | (unsigned)(~corig[nloc]);
                        if (key > best) best = key;
                    }
                }
            }
            #pragma unroll
            for (int o = 1; o < 4; o <<= 1) {
                unsigned long long v = __shfl_xor_sync(0xFFFFFFFFu, best, o);
                if (v > best) best = v;
            }
            if ((l & 3) == 0) {
                int qorig = qs[rowm];
                if (qorig >= 0 && best != 0ull) atomicMax(&g_keys[qorig], best);
            }
        }
    }
}

// ---------------- K5: output assembly, thread = (pixel, 8-channel group) -----
__global__ void output_kernel(const float* __restrict__ low,
                              float* __restrict__ out) {
    int pix = blockIdx.x * blockDim.x + threadIdx.x;
    if (pix >= HW) return;
    int y = pix / WW, x = pix % WW;
    int c0 = blockIdx.y * 8;

    int   offr[16];
    bool  ok[16];
    float cnt = 0.f;
    #pragma unroll
    for (int t = 0; t < 16; t++) {
        int di = t >> 2, dj = t & 3;
        int i = y - di, j = x - dj;
        bool o = (i >= 0) && (i < HP) && (j >= 0) && (j < HP);
        int p = o ? (i * HP + j) : 0;
        o = o && g_valid[p];
        ok[t] = o;
        int off = 0;
        if (o) {
            unsigned bp = (unsigned)(~g_keys[p]);   // low 32 bits = ~best_cand
            int bi = bp / HP, bj = bp % HP;
            off = (bi + di) * WW + (bj + dj);
            cnt += 1.f;
        }
        offr[t] = off;
    }

    if (cnt == 0.f) {
        #pragma unroll
        for (int c = 0; c < 8; c++)
            out[(c0 + c) * HW + pix] = low[(c0 + c) * HW + pix];
        return;
    }
    float inv = 1.f / (cnt + EPSF);
    #pragma unroll
    for (int c = 0; c < 8; c++) {
        const float* lc = low + (c0 + c) * HW;
        float a = 0.f;
        #pragma unroll
        for (int t = 0; t < 16; t++)
            if (ok[t]) a += lc[offr[t]];
        out[(c0 + c) * HW + pix] = a * inv;
    }
}

// ---------------- launcher ---------------------------------------------------
extern "C" void kernel_launch(void* const* d_in, const int* in_sizes, int n_in,
                              void* d_out, int out_size) {
    const float* low  = (const float*)d_in[0];
    const float* high = (const float*)d_in[1];
    const int*   mask = (const int*)d_in[2];
    float*       out  = (float*)d_out;

    cudaFuncSetAttribute(gemm_mma_kernel,
                         cudaFuncAttributeMaxDynamicSharedMemorySize, SMEM_TOTAL);

    sumsq_kernel<<<(HW + 255) / 256, 256>>>(low);
    stats_kernel<<<(NP + 255) / 256, 256>>>(mask);
    gather_split_kernel<<<dim3((NP + 1) / 2, 2), 256>>>(low, high);
    gemm_mma_kernel<<<148, 256, SMEM_TOTAL>>>();
    output_kernel<<<dim3((HW + 255) / 256, 4), 256>>>(low, out);
}